// round 13
// baseline (speedup 1.0000x reference)
#include <cuda_runtime.h>

#define NF      26
#define EMB     128
#define ROW_IN  (NF * EMB)               // 3328
#define NPAIR   325                      // 26*25/2
#define DENSE   128
#define ROW_OUT (ROW_IN + NPAIR + DENSE) // 3781
#define NB      11                       // ceil(325/32)
#define RPB     2                        // rows (warps) per block -> 64 threads

// compile-time pair decode: p in [0,325) -> (f,g), f<g, row-major upper triangle
__host__ __device__ constexpr int pf_(int p) {
    int f = 0, c = NF - 1;
    while (p >= c) { p -= c; f++; c--; }
    return f;
}
__host__ __device__ constexpr int pg_(int p) {
    int f = 0, c = NF - 1;
    while (p >= c) { p -= c; f++; c--; }
    return f + 1 + p;
}

// lane-local 4-element dot via packed f32x2 (sm_103a FFMA2 path; ptxas never
// auto-fuses this from scalar C++). a01/a23 hold elems {0,1}/{2,3} packed.
__device__ __forceinline__ float dot4(unsigned long long a01, unsigned long long a23,
                                      unsigned long long b01, unsigned long long b23)
{
    unsigned long long p;
    asm("mul.rn.f32x2 %0, %1, %2;" : "=l"(p) : "l"(a01), "l"(b01));
    asm("fma.rn.f32x2 %0, %1, %2, %0;" : "+l"(p) : "l"(a23), "l"(b23));
    return __uint_as_float((unsigned)p) + __uint_as_float((unsigned)(p >> 32));
}

// ---- static product fill for batch B, slot I ----
template<int B, int I>
__device__ __forceinline__ void batch_prods(const unsigned long long (&A01)[NF],
                                            const unsigned long long (&A23)[NF],
                                            float (&vals)[32])
{
    constexpr int p = B * 32 + I;
    if constexpr (p < NPAIR) {
        constexpr int f = pf_(p);
        constexpr int g = pg_(p);
        vals[I] = dot4(A01[f], A23[f], A01[g], A23[g]);
    } else {
        vals[I] = 0.f;
    }
    if constexpr (I + 1 < 32) batch_prods<B, I + 1>(A01, A23, vals);
}

// ---- batch B: products + 31-shuffle multi-value butterfly -> red[B] (lane j = output j) ----
template<int B>
__device__ __forceinline__ void gram_batches(const unsigned long long (&A01)[NF],
                                             const unsigned long long (&A23)[NF],
                                             float (&red)[NB], int lane)
{
    float vals[32];
    batch_prods<B, 0>(A01, A23, vals);

    #pragma unroll
    for (int m = 16; m >= 1; m >>= 1) {
        const bool hi = (lane & m) != 0;
        #pragma unroll
        for (int i = 0; i < m; i++) {
            float send = hi ? vals[i]     : vals[i + m];
            float keep = hi ? vals[i + m] : vals[i];
            vals[i] = keep + __shfl_xor_sync(0xFFFFFFFFu, send, m);
        }
    }
    red[B] = vals[0];

    if constexpr (B + 1 < NB) gram_batches<B + 1>(A01, A23, red, lane);
}

__global__ __launch_bounds__(RPB * 32)
void fi_kernel(const float* __restrict__ sparse,
               const float* __restrict__ dense,
               float* __restrict__ out,
               int batch)
{
    const int warp = threadIdx.x >> 5;
    const int lane = threadIdx.x & 31;
    const int r = blockIdx.x * RPB + warp;
    if (r >= batch) return;

    // lane l holds elements [4l, 4l+4) of every feature, packed as 2x f32x2
    unsigned long long A01[NF], A23[NF];
    float red[NB];

    const ulonglong2* __restrict__ in2 =
        (const ulonglong2*)(sparse + (size_t)r * ROW_IN);   // 16B-aligned: ROW_IN%4==0
    float* __restrict__ orow = out + (size_t)r * ROW_OUT;

    // ---- load row: 26x LDG.128, fully coalesced ----
    #pragma unroll
    for (int f = 0; f < NF; f++) {
        ulonglong2 v = in2[f * 32 + lane];
        A01[f] = v.x;
        A23[f] = v.y;
    }

    // ---- sparse passthrough straight from registers (scalar STG: out row base = r mod 4) ----
    #pragma unroll
    for (int f = 0; f < NF; f++) {
        const int o = f * EMB + 4 * lane;
        orow[o + 0] = __uint_as_float((unsigned)A01[f]);
        orow[o + 1] = __uint_as_float((unsigned)(A01[f] >> 32));
        orow[o + 2] = __uint_as_float((unsigned)A23[f]);
        orow[o + 3] = __uint_as_float((unsigned)(A23[f] >> 32));
    }

    // ---- dense passthrough ----
    {
        ulonglong2 dv = ((const ulonglong2*)(dense + (size_t)r * DENSE))[lane];
        const int o = ROW_IN + NPAIR + 4 * lane;
        orow[o + 0] = __uint_as_float((unsigned)dv.x);
        orow[o + 1] = __uint_as_float((unsigned)(dv.x >> 32));
        orow[o + 2] = __uint_as_float((unsigned)dv.y);
        orow[o + 3] = __uint_as_float((unsigned)(dv.y >> 32));
    }

    // ---- gram upper triangle: 11 fully static batches, single warp ----
    gram_batches<0>(A01, A23, red, lane);

    // ---- interaction stores: lane j holds output b*32+j -> coalesced ----
    #pragma unroll
    for (int b = 0; b < NB; b++) {
        const int idx = b * 32 + lane;
        if (idx < NPAIR) orow[ROW_IN + idx] = red[b];
    }
}

extern "C" void kernel_launch(void* const* d_in, const int* in_sizes, int n_in,
                              void* d_out, int out_size)
{
    const float* sparse = (const float*)d_in[0];
    const float* dense  = (const float*)d_in[1];
    float* out = (float*)d_out;

    const int batch = in_sizes[0] / ROW_IN;          // 16384
    const int grid  = (batch + RPB - 1) / RPB;       // 8192
    fi_kernel<<<grid, RPB * 32>>>(sparse, dense, out, batch);
}

// round 14
// speedup vs baseline: 1.0486x; 1.0486x over previous
#include <cuda_runtime.h>

#define NF      26
#define EMB     128
#define ROW_IN  (NF * EMB)               // 3328
#define NPAIR   325                      // 26*25/2
#define DENSE   128
#define ROW_OUT (ROW_IN + NPAIR + DENSE) // 3781
#define NB      11                       // ceil(325/32)
#define RPB     2                        // rows per block (2 warps each -> 128 thr)

// compile-time pair decode: p in [0,325) -> (f,g), f<g, row-major upper triangle
__host__ __device__ constexpr int pf_(int p) {
    int f = 0, c = NF - 1;
    while (p >= c) { p -= c; f++; c--; }
    return f;
}
__host__ __device__ constexpr int pg_(int p) {
    int f = 0, c = NF - 1;
    while (p >= c) { p -= c; f++; c--; }
    return f + 1 + p;
}

// ---- static product fill for batch B, slot I ----
template<int B, int I>
__device__ __forceinline__ void batch_prods(const float (&a0)[NF], const float (&a1)[NF],
                                            float (&vals)[32])
{
    constexpr int p = B * 32 + I;
    if constexpr (p < NPAIR) {
        constexpr int f = pf_(p);
        constexpr int g = pg_(p);
        vals[I] = a0[f] * a0[g] + a1[f] * a1[g];
    } else {
        vals[I] = 0.f;
    }
    if constexpr (I + 1 < 32) batch_prods<B, I + 1>(a0, a1, vals);
}

// ---- batch B: products + 31-shuffle multi-value butterfly; result (lane j = output j)
//      goes straight to this half-warp's smem staging slot (frees red[] registers) ----
template<int B>
__device__ __forceinline__ void gram_batches(const float (&a0)[NF], const float (&a1)[NF],
                                             float* __restrict__ s_out, int lane)
{
    float vals[32];
    batch_prods<B, 0>(a0, a1, vals);

    #pragma unroll
    for (int m = 16; m >= 1; m >>= 1) {
        const bool hi = (lane & m) != 0;
        #pragma unroll
        for (int i = 0; i < m; i++) {
            float send = hi ? vals[i]     : vals[i + m];
            float keep = hi ? vals[i + m] : vals[i];
            vals[i] = keep + __shfl_xor_sync(0xFFFFFFFFu, send, m);
        }
    }
    s_out[B * 32 + lane] = vals[0];      // static offset, immediate STS

    if constexpr (B + 1 < NB) gram_batches<B + 1>(a0, a1, s_out, lane);
}

__global__ __launch_bounds__(128, 5)
void fi_kernel(const float* __restrict__ sparse,
               const float* __restrict__ dense,
               float* __restrict__ out,
               int batch)
{
    // [row-in-block][half-warp][batch][lane]
    __shared__ float s_red[RPB][2][NB * 32];

    const int warp = threadIdx.x >> 5;
    const int lane = threadIdx.x & 31;
    const int rloc = warp >> 1;            // row within block
    const int half = warp & 1;             // which 64-element half of EMB
    const int r    = blockIdx.x * RPB + rloc;
    const bool active = r < batch;

    float a0[NF], a1[NF];
    float* __restrict__ orow = out + (size_t)r * ROW_OUT;

    if (active) {
        // lane l of half h holds elements {h*64+l, h*64+32+l} of every feature
        // (stride-1 across lanes: every LDG/STG is one full 128B line, full sectors)
        const float* __restrict__ in = sparse + (size_t)r * ROW_IN + half * 64 + lane;

        #pragma unroll
        for (int f = 0; f < NF; f++) {
            a0[f] = in[f * EMB];
            a1[f] = in[f * EMB + 32];
        }

        // sparse passthrough, coalesced from registers
        #pragma unroll
        for (int f = 0; f < NF; f++) {
            orow[f * EMB + half * 64 + lane]      = a0[f];
            orow[f * EMB + half * 64 + 32 + lane] = a1[f];
        }

        // dense passthrough
        {
            const float* __restrict__ dr = dense + (size_t)r * DENSE + half * 64 + lane;
            orow[ROW_IN + NPAIR + half * 64 + lane]      = dr[0];
            orow[ROW_IN + NPAIR + half * 64 + 32 + lane] = dr[32];
        }

        // gram upper triangle: 11 fully static batches; results staged to smem
        gram_batches<0>(a0, a1, &s_red[rloc][half][0], lane);
    }

    __syncthreads();

    // cross-warp combine: half-warps split the batches (even -> half 0, odd -> half 1)
    if (active) {
        #pragma unroll
        for (int b = 0; b < NB; b++) {
            if ((b & 1) == half) {
                const int idx = b * 32 + lane;
                if (idx < NPAIR) {
                    orow[ROW_IN + idx] = s_red[rloc][0][b * 32 + lane]
                                       + s_red[rloc][1][b * 32 + lane];
                }
            }
        }
    }
}

extern "C" void kernel_launch(void* const* d_in, const int* in_sizes, int n_in,
                              void* d_out, int out_size)
{
    const float* sparse = (const float*)d_in[0];
    const float* dense  = (const float*)d_in[1];
    float* out = (float*)d_out;

    const int batch = in_sizes[0] / ROW_IN;          // 16384
    const int grid  = (batch + RPB - 1) / RPB;       // 8192
    fi_kernel<<<grid, RPB * 2 * 32>>>(sparse, dense, out, batch);
}